// round 3
// baseline (speedup 1.0000x reference)
#include <cuda_runtime.h>

#define NN 50000
#define EE 800000
#define HIDD 64
#define HC 256

// ---------------- device scratch (static, no allocation) ----------------
__device__ __align__(16) float g_x[NN * HC];        // per-layer features [N,H*C]
__device__ __align__(16) float g_ae[EE * 4];        // edge attn logits
__device__ __align__(16) float g_alpha[EE * 4];     // alpha, then exp(alpha-max)
__device__ __align__(16) float g_asrc[NN * 4];
__device__ __align__(16) float g_adst[NN * 4];
__device__ unsigned g_amax[NN * 4];
__device__ float g_denom[NN * 4];
__device__ __align__(16) float g_zbuf[NN * HIDD];   // inter-layer z
__device__ int g_src[EE];
__device__ int g_dst[EE];
__device__ int g_eid[EE];                           // CSR edge ids (by dst)
__device__ int g_deg[NN];
__device__ int g_excl[NN];
__device__ int g_rowptr[NN + 1];
__device__ int g_wpos[NN];
__device__ int g_btot[64];
__device__ int g_boff[64];
__device__ float g_Wae[24];                         // [L][3][4]
__device__ int g_is32;                              // edge_index dtype flag

// ---------------- helpers ----------------
__device__ __forceinline__ unsigned fkey(float f) {
    unsigned u = __float_as_uint(f);
    return (u & 0x80000000u) ? ~u : (u | 0x80000000u);
}
__device__ __forceinline__ float fdec(unsigned u) {
    return (u & 0x80000000u) ? __uint_as_float(u ^ 0x80000000u) : __uint_as_float(~u);
}
__device__ __forceinline__ float lrelu(float v) { return v > 0.f ? v : 0.2f * v; }

// ---------------- dtype detect: int64 vs int32 edge_index ----------------
__global__ void k_detect(const void* __restrict__ ei) {
    // If interpreted as int64 any of the first 1024 values is out of [0,NN),
    // the buffer is actually int32. (Random int32 pairs in [0,50000) always
    // produce int64 values >= 2^32 when the odd element is nonzero; at least
    // one of 1024 is nonzero with overwhelming certainty — and if ALL odd
    // elements were zero the int64 interpretation is numerically identical.)
    if (threadIdx.x == 0) g_is32 = 0;
    __syncthreads();
    const long long* p = (const long long*)ei;
    long long v = p[threadIdx.x];
    if (v < 0 || v >= NN) atomicExch(&g_is32, 1);
}

// ---------------- CSR build ----------------
__global__ void k_zero_deg() {
    int i = blockIdx.x * blockDim.x + threadIdx.x;
    if (i < NN) g_deg[i] = 0;
}

__global__ void k_convert(const void* __restrict__ ei) {
    int e = blockIdx.x * blockDim.x + threadIdx.x;
    if (e >= EE) return;
    int s, d;
    if (g_is32) {
        const int* p = (const int*)ei;
        s = p[e];
        d = p[EE + e];
    } else {
        const long long* p = (const long long*)ei;
        s = (int)p[e];
        d = (int)p[EE + e];
    }
    // clamp defensively (avoid wild atomics even if detection is wrong)
    s = (s < 0) ? 0 : (s >= NN ? NN - 1 : s);
    d = (d < 0) ? 0 : (d >= NN ? NN - 1 : d);
    g_src[e] = s;
    g_dst[e] = d;
    atomicAdd(&g_deg[d], 1);
}

__global__ void k_scan1() {
    __shared__ int s[1024];
    int t = threadIdx.x;
    int i = blockIdx.x * 1024 + t;
    int v = (i < NN) ? g_deg[i] : 0;
    s[t] = v;
    __syncthreads();
    for (int off = 1; off < 1024; off <<= 1) {
        int tv = (t >= off) ? s[t - off] : 0;
        __syncthreads();
        s[t] += tv;
        __syncthreads();
    }
    if (i < NN) g_excl[i] = s[t] - v;
    if (t == 1023) g_btot[blockIdx.x] = s[1023];
}

__global__ void k_scan2(int nb) {
    if (threadIdx.x == 0) {
        int run = 0;
        for (int b = 0; b < nb; b++) { g_boff[b] = run; run += g_btot[b]; }
        g_rowptr[NN] = run;
    }
}

__global__ void k_scan3() {
    int i = blockIdx.x * blockDim.x + threadIdx.x;
    if (i < NN) {
        int v = g_excl[i] + g_boff[i >> 10];
        g_rowptr[i] = v;
        g_wpos[i] = v;
    }
}

__global__ void k_scatter() {
    int e = blockIdx.x * blockDim.x + threadIdx.x;
    if (e >= EE) return;
    int d = g_dst[e];
    int p = atomicAdd(&g_wpos[d], 1);
    g_eid[p] = e;
}

// ---------------- tiny weight folds ----------------
// W_ae[l][d][h] = sum_c att_edge[l,h,c] * lin_edge_W[l, h*64+c, d]
__global__ void k_wae(const float* __restrict__ att_edge,
                      const float* __restrict__ lin_edge_W) {
    int t = threadIdx.x;
    if (t >= 24) return;
    int l = t / 12;
    int r = t % 12;
    int d = r / 4;
    int h = r % 4;
    float acc = 0.f;
    for (int c = 0; c < 64; c++)
        acc += att_edge[l * 256 + h * 64 + c] * lin_edge_W[l * 768 + (h * 64 + c) * 3 + d];
    g_Wae[l * 12 + d * 4 + h] = acc;
}

__global__ void k_ae(int l, const float* __restrict__ ea) {
    int e = blockIdx.x * blockDim.x + threadIdx.x;
    if (e >= EE) return;
    float e0 = ea[3 * e], e1 = ea[3 * e + 1], e2 = ea[3 * e + 2];
    const float* W = g_Wae + l * 12;
    float4 out;
    out.x = e0 * W[0] + e1 * W[4] + e2 * W[8];
    out.y = e0 * W[1] + e1 * W[5] + e2 * W[9];
    out.z = e0 * W[2] + e1 * W[6] + e2 * W[10];
    out.w = e0 * W[3] + e1 * W[7] + e2 * W[11];
    *reinterpret_cast<float4*>(g_ae + 4 * e) = out;
}

__global__ void k_zero_nd() {
    int i = blockIdx.x * blockDim.x + threadIdx.x;
    if (i < NN * 4) { g_amax[i] = 0u; g_denom[i] = 0.f; }
}

// ---------------- GEMM: x = z @ W^T, fused a_src/a_dst ----------------
// blockIdx.y = column half (128 cols = 2 heads). Static smem only (33.8 KB).
// Warp handles 4 nodes; lane owns cols lane+32*j (j=0..3) within the half.
__global__ void k_gemm(const float* __restrict__ hin, int layer,
                       const float* __restrict__ linW,
                       const float* __restrict__ attS,
                       const float* __restrict__ attD) {
    __shared__ float Wsm[64 * 132];  // [64 k][128 cols + pad 4]
    const int half = blockIdx.y;
    const float* zin = (layer == 0) ? hin : g_zbuf;
    int tid = threadIdx.x;
    for (int idx = tid; idx < 128 * 64; idx += 256) {
        int k = idx & 63;
        int j = idx >> 6;
        Wsm[k * 132 + j] = linW[(half * 128 + j) * 64 + k];
    }
    __syncthreads();
    int lane = tid & 31;
    int gw = blockIdx.x * 8 + (tid >> 5);
    int nw = gridDim.x * 8;
    for (int n4 = gw * 4; n4 < NN; n4 += nw * 4) {
        float z0[4], z1[4];
#pragma unroll
        for (int i = 0; i < 4; i++) {
            z0[i] = zin[(n4 + i) * 64 + lane];
            z1[i] = zin[(n4 + i) * 64 + 32 + lane];
        }
        float acc[4][4];
#pragma unroll
        for (int i = 0; i < 4; i++)
#pragma unroll
            for (int j = 0; j < 4; j++) acc[i][j] = 0.f;
#pragma unroll
        for (int k = 0; k < 64; k++) {
            float zk[4];
#pragma unroll
            for (int i = 0; i < 4; i++)
                zk[i] = __shfl_sync(0xffffffffu, (k < 32) ? z0[i] : z1[i], k & 31);
#pragma unroll
            for (int j = 0; j < 4; j++) {
                float wv = Wsm[k * 132 + lane + 32 * j];
#pragma unroll
                for (int i = 0; i < 4; i++) acc[i][j] = fmaf(zk[i], wv, acc[i][j]);
            }
        }
#pragma unroll
        for (int i = 0; i < 4; i++) {
            int n = n4 + i;
#pragma unroll
            for (int j = 0; j < 4; j++)
                g_x[n * 256 + half * 128 + lane + 32 * j] = acc[i][j];
            float ps[2], pd[2];
#pragma unroll
            for (int hl = 0; hl < 2; hl++) {
                int h = half * 2 + hl;
                float s0 = attS[h * 64 + lane], s1 = attS[h * 64 + 32 + lane];
                float d0 = attD[h * 64 + lane], d1 = attD[h * 64 + 32 + lane];
                ps[hl] = acc[i][2 * hl] * s0 + acc[i][2 * hl + 1] * s1;
                pd[hl] = acc[i][2 * hl] * d0 + acc[i][2 * hl + 1] * d1;
            }
#pragma unroll
            for (int hl = 0; hl < 2; hl++) {
#pragma unroll
                for (int off = 16; off > 0; off >>= 1) {
                    ps[hl] += __shfl_xor_sync(0xffffffffu, ps[hl], off);
                    pd[hl] += __shfl_xor_sync(0xffffffffu, pd[hl], off);
                }
            }
            if (lane == 0) {
                *reinterpret_cast<float2*>(g_asrc + 4 * n + half * 2) = make_float2(ps[0], ps[1]);
                *reinterpret_cast<float2*>(g_adst + 4 * n + half * 2) = make_float2(pd[0], pd[1]);
            }
        }
    }
}

// ---------------- pass A: alpha + segment max ----------------
__global__ void k_passA() {
    int e = blockIdx.x * blockDim.x + threadIdx.x;
    if (e >= EE) return;
    int s = g_src[e], d = g_dst[e];
    float4 ae = *reinterpret_cast<const float4*>(g_ae + 4 * e);
    float4 as = *reinterpret_cast<const float4*>(g_asrc + 4 * s);
    float4 ad = *reinterpret_cast<const float4*>(g_adst + 4 * d);
    float4 al;
    al.x = lrelu(as.x + ad.x + ae.x);
    al.y = lrelu(as.y + ad.y + ae.y);
    al.z = lrelu(as.z + ad.z + ae.z);
    al.w = lrelu(as.w + ad.w + ae.w);
    *reinterpret_cast<float4*>(g_alpha + 4 * e) = al;
    atomicMax(&g_amax[4 * d + 0], fkey(al.x));
    atomicMax(&g_amax[4 * d + 1], fkey(al.y));
    atomicMax(&g_amax[4 * d + 2], fkey(al.z));
    atomicMax(&g_amax[4 * d + 3], fkey(al.w));
}

// ---------------- pass B: exp + segment sum ----------------
__global__ void k_passB() {
    int e = blockIdx.x * blockDim.x + threadIdx.x;
    if (e >= EE) return;
    int d = g_dst[e];
    float4 al = *reinterpret_cast<const float4*>(g_alpha + 4 * e);
    float m0 = fdec(g_amax[4 * d + 0]);
    float m1 = fdec(g_amax[4 * d + 1]);
    float m2 = fdec(g_amax[4 * d + 2]);
    float m3 = fdec(g_amax[4 * d + 3]);
    float4 ex;
    ex.x = __expf(al.x - m0);
    ex.y = __expf(al.y - m1);
    ex.z = __expf(al.z - m2);
    ex.w = __expf(al.w - m3);
    *reinterpret_cast<float4*>(g_alpha + 4 * e) = ex;
    atomicAdd(&g_denom[4 * d + 0], ex.x);
    atomicAdd(&g_denom[4 * d + 1], ex.y);
    atomicAdd(&g_denom[4 * d + 2], ex.z);
    atomicAdd(&g_denom[4 * d + 3], ex.w);
}

// ---------------- aggregation: warp per dst node, fused mean+LN+SiLU ----
__global__ void k_agg(const float* __restrict__ bias, const float* __restrict__ gamma,
                      const float* __restrict__ beta, float* __restrict__ dout, int layer) {
    int gtid = blockIdx.x * blockDim.x + threadIdx.x;
    int n = gtid >> 5;
    if (n >= NN) return;
    int lane = gtid & 31;
    int hd = lane >> 3;
    int sub = lane & 7;
    int beg = g_rowptr[n], end = g_rowptr[n + 1];
    float den = g_denom[4 * n + hd];
    float invd = 1.f / (den + 1e-16f);
    float4 a0 = make_float4(0.f, 0.f, 0.f, 0.f);
    float4 a1 = make_float4(0.f, 0.f, 0.f, 0.f);
    for (int p = beg; p < end; ++p) {
        int e = g_eid[p];
        int s = g_src[e];
        float w = g_alpha[4 * e + hd] * invd;
        const float4* xp = reinterpret_cast<const float4*>(g_x + s * 256 + lane * 8);
        float4 v0 = xp[0];
        float4 v1 = xp[1];
        a0.x = fmaf(w, v0.x, a0.x);
        a0.y = fmaf(w, v0.y, a0.y);
        a0.z = fmaf(w, v0.z, a0.z);
        a0.w = fmaf(w, v0.w, a0.w);
        a1.x = fmaf(w, v1.x, a1.x);
        a1.y = fmaf(w, v1.y, a1.y);
        a1.z = fmaf(w, v1.z, a1.z);
        a1.w = fmaf(w, v1.w, a1.w);
    }
    // sum across heads (lanes sub, sub+8, sub+16, sub+24 hold same channels)
#define REDH(c)                                      \
    c += __shfl_xor_sync(0xffffffffu, c, 8);         \
    c += __shfl_xor_sync(0xffffffffu, c, 16);
    REDH(a0.x) REDH(a0.y) REDH(a0.z) REDH(a0.w)
    REDH(a1.x) REDH(a1.y) REDH(a1.z) REDH(a1.w)
#undef REDH
    float out[8] = {a0.x, a0.y, a0.z, a0.w, a1.x, a1.y, a1.z, a1.w};
    float s1 = 0.f, s2 = 0.f;
#pragma unroll
    for (int i = 0; i < 8; i++) {
        out[i] = out[i] * 0.25f + bias[sub * 8 + i];
        s1 += out[i];
        s2 += out[i] * out[i];
    }
#pragma unroll
    for (int off = 1; off <= 4; off <<= 1) {
        s1 += __shfl_xor_sync(0xffffffffu, s1, off);
        s2 += __shfl_xor_sync(0xffffffffu, s2, off);
    }
    float mu = s1 * (1.f / 64.f);
    float var = s2 * (1.f / 64.f) - mu * mu;
    float rstd = rsqrtf(var + 1e-5f);
    float* zout = (layer == 1) ? dout : g_zbuf;
    if (lane < 8) {
        float res[8];
#pragma unroll
        for (int i = 0; i < 8; i++) {
            int c = sub * 8 + i;
            float ln = (out[i] - mu) * rstd * gamma[c] + beta[c];
            res[i] = ln / (1.f + __expf(-ln));
        }
        float4* op = reinterpret_cast<float4*>(zout + n * 64 + sub * 8);
        op[0] = make_float4(res[0], res[1], res[2], res[3]);
        op[1] = make_float4(res[4], res[5], res[6], res[7]);
    }
}

// ---------------- launch ----------------
extern "C" void kernel_launch(void* const* d_in, const int* in_sizes, int n_in,
                              void* d_out, int out_size) {
    const float* h = (const float*)d_in[1];
    const void* ei = d_in[2];
    const float* ea = (const float*)d_in[3];
    const float* linW = (const float*)d_in[4];
    const float* linEW = (const float*)d_in[5];
    const float* attS = (const float*)d_in[6];
    const float* attD = (const float*)d_in[7];
    const float* attE = (const float*)d_in[8];
    const float* bias = (const float*)d_in[9];
    const float* gamma = (const float*)d_in[10];
    const float* beta = (const float*)d_in[11];
    float* dout = (float*)d_out;

    // CSR build (cheap; graph identical each call -> deterministic sizes)
    k_detect<<<1, 1024>>>(ei);
    k_zero_deg<<<(NN + 255) / 256, 256>>>();
    k_convert<<<(EE + 255) / 256, 256>>>(ei);
    k_scan1<<<(NN + 1023) / 1024, 1024>>>();
    k_scan2<<<1, 32>>>((NN + 1023) / 1024);
    k_scan3<<<(NN + 255) / 256, 256>>>();
    k_scatter<<<(EE + 255) / 256, 256>>>();
    k_wae<<<1, 32>>>(attE, linEW);

    for (int l = 0; l < 2; l++) {
        k_zero_nd<<<(NN * 4 + 255) / 256, 256>>>();
        k_ae<<<(EE + 255) / 256, 256>>>(l, ea);
        k_gemm<<<dim3(296, 2), 256>>>(h, l, linW + l * 256 * 64, attS + l * 256, attD + l * 256);
        k_passA<<<(EE + 255) / 256, 256>>>();
        k_passB<<<(EE + 255) / 256, 256>>>();
        k_agg<<<(NN * 32 + 255) / 256, 256>>>(bias + l * 64, gamma + l * 64, beta + l * 64, dout, l);
    }
}

// round 4
// speedup vs baseline: 1.4387x; 1.4387x over previous
#include <cuda_runtime.h>
#include <cuda_fp16.h>

#define NN 50000
#define EE 800000
#define HIDD 64
#define HC 256

// ---------------- device scratch (static, no allocation) ----------------
__device__ __align__(16) __half g_xh[NN * HC];      // per-layer features [N,H*C] fp16
__device__ __align__(16) float g_alphap[EE * 4];    // alpha in CSR order [p][4]
__device__ int g_srcp[EE];                          // src per CSR position
__device__ __align__(16) float g_asrc[NN * 4];
__device__ __align__(16) float g_adst[NN * 4];
__device__ __align__(16) float g_zbuf[NN * HIDD];   // inter-layer z
__device__ int g_src[EE];
__device__ int g_dst[EE];
__device__ int g_eid[EE];                           // CSR edge ids (by dst)
__device__ int g_deg[NN];
__device__ int g_excl[NN];
__device__ int g_rowptr[NN + 1];
__device__ int g_wpos[NN];
__device__ int g_btot[64];
__device__ int g_boff[64];
__device__ float g_Wae[24];                         // [L][3][4]
__device__ int g_is32;                              // edge_index dtype flag

__device__ __forceinline__ float lrelu(float v) { return v > 0.f ? v : 0.2f * v; }

// ---------------- dtype detect: int64 vs int32 edge_index ----------------
__global__ void k_detect(const void* __restrict__ ei) {
    if (threadIdx.x == 0) g_is32 = 0;
    __syncthreads();
    const long long* p = (const long long*)ei;
    long long v = p[threadIdx.x];
    if (v < 0 || v >= NN) atomicExch(&g_is32, 1);
}

// ---------------- CSR build ----------------
__global__ void k_zero_deg() {
    int i = blockIdx.x * blockDim.x + threadIdx.x;
    if (i < NN) g_deg[i] = 0;
}

__global__ void k_convert(const void* __restrict__ ei) {
    int e = blockIdx.x * blockDim.x + threadIdx.x;
    if (e >= EE) return;
    int s, d;
    if (g_is32) {
        const int* p = (const int*)ei;
        s = p[e];
        d = p[EE + e];
    } else {
        const long long* p = (const long long*)ei;
        s = (int)p[e];
        d = (int)p[EE + e];
    }
    s = (s < 0) ? 0 : (s >= NN ? NN - 1 : s);
    d = (d < 0) ? 0 : (d >= NN ? NN - 1 : d);
    g_src[e] = s;
    g_dst[e] = d;
    atomicAdd(&g_deg[d], 1);
}

__global__ void k_scan1() {
    __shared__ int s[1024];
    int t = threadIdx.x;
    int i = blockIdx.x * 1024 + t;
    int v = (i < NN) ? g_deg[i] : 0;
    s[t] = v;
    __syncthreads();
    for (int off = 1; off < 1024; off <<= 1) {
        int tv = (t >= off) ? s[t - off] : 0;
        __syncthreads();
        s[t] += tv;
        __syncthreads();
    }
    if (i < NN) g_excl[i] = s[t] - v;
    if (t == 1023) g_btot[blockIdx.x] = s[1023];
}

__global__ void k_scan2(int nb) {
    if (threadIdx.x == 0) {
        int run = 0;
        for (int b = 0; b < nb; b++) { g_boff[b] = run; run += g_btot[b]; }
        g_rowptr[NN] = run;
    }
}

__global__ void k_scan3() {
    int i = blockIdx.x * blockDim.x + threadIdx.x;
    if (i < NN) {
        int v = g_excl[i] + g_boff[i >> 10];
        g_rowptr[i] = v;
        g_wpos[i] = v;
    }
}

__global__ void k_scatter() {
    int e = blockIdx.x * blockDim.x + threadIdx.x;
    if (e >= EE) return;
    int d = g_dst[e];
    int p = atomicAdd(&g_wpos[d], 1);
    g_eid[p] = e;
}

// ---------------- tiny weight folds ----------------
__global__ void k_wae(const float* __restrict__ att_edge,
                      const float* __restrict__ lin_edge_W) {
    int t = threadIdx.x;
    if (t >= 24) return;
    int l = t / 12;
    int r = t % 12;
    int d = r / 4;
    int h = r % 4;
    float acc = 0.f;
    for (int c = 0; c < 64; c++)
        acc += att_edge[l * 256 + h * 64 + c] * lin_edge_W[l * 768 + (h * 64 + c) * 3 + d];
    g_Wae[l * 12 + d * 4 + h] = acc;
}

// ---------------- GEMM: x = z @ W^T (fp16 out), fused a_src/a_dst ------
__global__ void k_gemm(const float* __restrict__ hin, int layer,
                       const float* __restrict__ linW,
                       const float* __restrict__ attS,
                       const float* __restrict__ attD) {
    __shared__ float Wsm[64 * 132];  // [64 k][128 cols + pad 4]
    const int half_ = blockIdx.y;
    const float* zin = (layer == 0) ? hin : g_zbuf;
    int tid = threadIdx.x;
    for (int idx = tid; idx < 128 * 64; idx += 256) {
        int k = idx & 63;
        int j = idx >> 6;
        Wsm[k * 132 + j] = linW[(half_ * 128 + j) * 64 + k];
    }
    __syncthreads();
    int lane = tid & 31;
    int gw = blockIdx.x * 8 + (tid >> 5);
    int nw = gridDim.x * 8;
    for (int n4 = gw * 4; n4 < NN; n4 += nw * 4) {
        float z0[4], z1[4];
#pragma unroll
        for (int i = 0; i < 4; i++) {
            z0[i] = zin[(n4 + i) * 64 + lane];
            z1[i] = zin[(n4 + i) * 64 + 32 + lane];
        }
        float acc[4][4];
#pragma unroll
        for (int i = 0; i < 4; i++)
#pragma unroll
            for (int j = 0; j < 4; j++) acc[i][j] = 0.f;
#pragma unroll
        for (int k = 0; k < 64; k++) {
            float zk[4];
#pragma unroll
            for (int i = 0; i < 4; i++)
                zk[i] = __shfl_sync(0xffffffffu, (k < 32) ? z0[i] : z1[i], k & 31);
#pragma unroll
            for (int j = 0; j < 4; j++) {
                float wv = Wsm[k * 132 + lane + 32 * j];
#pragma unroll
                for (int i = 0; i < 4; i++) acc[i][j] = fmaf(zk[i], wv, acc[i][j]);
            }
        }
#pragma unroll
        for (int i = 0; i < 4; i++) {
            int n = n4 + i;
#pragma unroll
            for (int j = 0; j < 4; j++)
                g_xh[n * 256 + half_ * 128 + lane + 32 * j] = __float2half(acc[i][j]);
            float ps[2], pd[2];
#pragma unroll
            for (int hl = 0; hl < 2; hl++) {
                int h = half_ * 2 + hl;
                float s0 = attS[h * 64 + lane], s1 = attS[h * 64 + 32 + lane];
                float d0 = attD[h * 64 + lane], d1 = attD[h * 64 + 32 + lane];
                ps[hl] = acc[i][2 * hl] * s0 + acc[i][2 * hl + 1] * s1;
                pd[hl] = acc[i][2 * hl] * d0 + acc[i][2 * hl + 1] * d1;
            }
#pragma unroll
            for (int hl = 0; hl < 2; hl++) {
#pragma unroll
                for (int off = 16; off > 0; off >>= 1) {
                    ps[hl] += __shfl_xor_sync(0xffffffffu, ps[hl], off);
                    pd[hl] += __shfl_xor_sync(0xffffffffu, pd[hl], off);
                }
            }
            if (lane == 0) {
                *reinterpret_cast<float2*>(g_asrc + 4 * n + half_ * 2) = make_float2(ps[0], ps[1]);
                *reinterpret_cast<float2*>(g_adst + 4 * n + half_ * 2) = make_float2(pd[0], pd[1]);
            }
        }
    }
}

// ---------------- pass A: alpha in CSR order (no atomics) ----------------
__global__ void k_passA(int l, const float* __restrict__ ea) {
    int p = blockIdx.x * blockDim.x + threadIdx.x;
    if (p >= EE) return;
    int e = g_eid[p];
    int s = g_src[e], d = g_dst[e];
    float e0 = ea[3 * e], e1 = ea[3 * e + 1], e2 = ea[3 * e + 2];
    const float* W = g_Wae + l * 12;
    float4 as = *reinterpret_cast<const float4*>(g_asrc + 4 * s);
    float4 ad = *reinterpret_cast<const float4*>(g_adst + 4 * d);
    float4 al;
    al.x = lrelu(as.x + ad.x + e0 * W[0] + e1 * W[4] + e2 * W[8]);
    al.y = lrelu(as.y + ad.y + e0 * W[1] + e1 * W[5] + e2 * W[9]);
    al.z = lrelu(as.z + ad.z + e0 * W[2] + e1 * W[6] + e2 * W[10]);
    al.w = lrelu(as.w + ad.w + e0 * W[3] + e1 * W[7] + e2 * W[11]);
    *reinterpret_cast<float4*>(g_alphap + 4 * p) = al;
    g_srcp[p] = s;
}

// ---------------- aggregation: warp per dst node, inline softmax --------
__global__ void k_agg(const float* __restrict__ bias, const float* __restrict__ gamma,
                      const float* __restrict__ beta, float* __restrict__ dout, int layer) {
    int gtid = blockIdx.x * blockDim.x + threadIdx.x;
    int n = gtid >> 5;
    if (n >= NN) return;
    int lane = gtid & 31;
    int hd = lane >> 3;
    int sub = lane & 7;
    int beg = g_rowptr[n], end = g_rowptr[n + 1];
    int deg = end - beg;

    // loop 1: softmax denominator (lane l accumulates head l&3)
    float dacc = 0.f;
    for (int idx = lane; idx < deg * 4; idx += 32)
        dacc += __expf(g_alphap[beg * 4 + idx]);
    dacc += __shfl_xor_sync(0xffffffffu, dacc, 4);
    dacc += __shfl_xor_sync(0xffffffffu, dacc, 8);
    dacc += __shfl_xor_sync(0xffffffffu, dacc, 16);
    float den = __shfl_sync(0xffffffffu, dacc, hd);  // lanes 0..3 hold heads 0..3
    float invd = 1.f / (den + 1e-16f);

    // loop 2: weighted gather of fp16 x rows
    float a[8] = {0.f, 0.f, 0.f, 0.f, 0.f, 0.f, 0.f, 0.f};
    for (int p = beg; p < end; ++p) {
        int s = g_srcp[p];
        float w = __expf(g_alphap[4 * p + hd]) * invd;
        uint4 raw = *reinterpret_cast<const uint4*>(g_xh + s * 256 + lane * 8);
        const __half2* h2 = reinterpret_cast<const __half2*>(&raw);
#pragma unroll
        for (int q = 0; q < 4; q++) {
            float2 f = __half22float2(h2[q]);
            a[2 * q] = fmaf(w, f.x, a[2 * q]);
            a[2 * q + 1] = fmaf(w, f.y, a[2 * q + 1]);
        }
    }
    // sum across heads (lanes sub, sub+8, sub+16, sub+24 hold same channels)
#pragma unroll
    for (int q = 0; q < 8; q++) {
        a[q] += __shfl_xor_sync(0xffffffffu, a[q], 8);
        a[q] += __shfl_xor_sync(0xffffffffu, a[q], 16);
    }
    float s1 = 0.f, s2 = 0.f;
#pragma unroll
    for (int i = 0; i < 8; i++) {
        a[i] = a[i] * 0.25f + bias[sub * 8 + i];
        s1 += a[i];
        s2 += a[i] * a[i];
    }
#pragma unroll
    for (int off = 1; off <= 4; off <<= 1) {
        s1 += __shfl_xor_sync(0xffffffffu, s1, off);
        s2 += __shfl_xor_sync(0xffffffffu, s2, off);
    }
    float mu = s1 * (1.f / 64.f);
    float var = s2 * (1.f / 64.f) - mu * mu;
    float rstd = rsqrtf(var + 1e-5f);
    float* zout = (layer == 1) ? dout : g_zbuf;
    if (lane < 8) {
        float res[8];
#pragma unroll
        for (int i = 0; i < 8; i++) {
            int c = sub * 8 + i;
            float ln = (a[i] - mu) * rstd * gamma[c] + beta[c];
            res[i] = ln / (1.f + __expf(-ln));
        }
        float4* op = reinterpret_cast<float4*>(zout + n * 64 + sub * 8);
        op[0] = make_float4(res[0], res[1], res[2], res[3]);
        op[1] = make_float4(res[4], res[5], res[6], res[7]);
    }
}

// ---------------- launch ----------------
extern "C" void kernel_launch(void* const* d_in, const int* in_sizes, int n_in,
                              void* d_out, int out_size) {
    const float* h = (const float*)d_in[1];
    const void* ei = d_in[2];
    const float* ea = (const float*)d_in[3];
    const float* linW = (const float*)d_in[4];
    const float* linEW = (const float*)d_in[5];
    const float* attS = (const float*)d_in[6];
    const float* attD = (const float*)d_in[7];
    const float* attE = (const float*)d_in[8];
    const float* bias = (const float*)d_in[9];
    const float* gamma = (const float*)d_in[10];
    const float* beta = (const float*)d_in[11];
    float* dout = (float*)d_out;

    k_detect<<<1, 1024>>>(ei);
    k_zero_deg<<<(NN + 255) / 256, 256>>>();
    k_convert<<<(EE + 255) / 256, 256>>>(ei);
    k_scan1<<<(NN + 1023) / 1024, 1024>>>();
    k_scan2<<<1, 32>>>((NN + 1023) / 1024);
    k_scan3<<<(NN + 255) / 256, 256>>>();
    k_scatter<<<(EE + 255) / 256, 256>>>();
    k_wae<<<1, 32>>>(attE, linEW);

    for (int l = 0; l < 2; l++) {
        k_gemm<<<dim3(296, 2), 256>>>(h, l, linW + l * 256 * 64, attS + l * 256, attD + l * 256);
        k_passA<<<(EE + 255) / 256, 256>>>(l, ea);
        k_agg<<<(NN * 32 + 255) / 256, 256>>>(bias + l * 64, gamma + l * 64, beta + l * 64, dout, l);
    }
}